// round 1
// baseline (speedup 1.0000x reference)
#include <cuda_runtime.h>
#include <cstdint>

#define NPTS 8192
#define DIMX 256
#define DIMZ 64
#define KNN  5
#define EPSF 1e-7f
#define TILE 64
#define BK   8
#define LDA  72   // padded smem stride (keeps 16B alignment: 72*4=288)

// ---- scratch (static device globals; no allocations allowed) ----
__device__ float g_sq[NPTS];
__device__ float g_lidX[NPTS];
__device__ int   g_nn[NPTS * KNN];
__device__ float g_diff2[NPTS];

// ---- packed fp32x2 helpers (FFMA2 path, 2x fp32 FMA throughput) ----
__device__ __forceinline__ unsigned long long pack2(float lo, float hi) {
    unsigned long long r;
    asm("mov.b64 %0, {%1, %2};" : "=l"(r) : "f"(lo), "f"(hi));
    return r;
}
__device__ __forceinline__ void unpack2(unsigned long long v, float& lo, float& hi) {
    asm("mov.b64 {%0, %1}, %2;" : "=f"(lo), "=f"(hi) : "l"(v));
}
#define FMA2(d, a, b) \
    asm("fma.rn.f32x2 %0, %1, %2, %3;" : "=l"(d) : "l"(a), "l"(b), "l"(d))

// lexicographic (value, index) compare: matches jax.lax.top_k tie-breaking
__device__ __forceinline__ bool lessp(float v, int i, float v2, int i2) {
    return (v < v2) || (v == v2 && i < i2);
}

// sorted insert into ascending top-KNN list (register resident, fully unrolled)
__device__ __forceinline__ void insert5(float lv[KNN], int li[KNN], float v, int idx) {
    if (lessp(v, idx, lv[KNN - 1], li[KNN - 1])) {
        lv[KNN - 1] = v; li[KNN - 1] = idx;
#pragma unroll
        for (int s = KNN - 1; s > 0; --s) {
            if (lessp(lv[s], li[s], lv[s - 1], li[s - 1])) {
                float tv = lv[s]; lv[s] = lv[s - 1]; lv[s - 1] = tv;
                int   ti = li[s]; li[s] = li[s - 1]; li[s - 1] = ti;
            }
        }
    }
}

// ---- kernel A: squared row norms of X ----
__global__ void sq_kernel(const float* __restrict__ X) {
    int warp = (blockIdx.x * blockDim.x + threadIdx.x) >> 5;
    int lane = threadIdx.x & 31;
    if (warp >= NPTS) return;
    const float* row = X + (size_t)warp * DIMX;
    float s = 0.f;
#pragma unroll
    for (int t = 0; t < DIMX / 32; ++t) {
        float v = row[lane + 32 * t];
        s = fmaf(v, v, s);
    }
#pragma unroll
    for (int o = 16; o > 0; o >>= 1) s += __shfl_xor_sync(0xffffffffu, s, o);
    if (lane == 0) g_sq[warp] = s;
}

// ---- kernel B: fused X Gram (f32x2 FMA) + per-row top-5 NN + lid_X ----
__global__ __launch_bounds__(256) void knn_kernel(const float* __restrict__ X) {
    __shared__ __align__(16) float As[BK][LDA];
    __shared__ __align__(16) float Bs[BK][LDA];

    const int tx = threadIdx.x & 15;   // column group 0..15
    const int ty = threadIdx.x >> 4;   // row group    0..15
    const int rowBase = blockIdx.x * TILE;

    // loader mapping: each thread loads 2 elems of A-tile and 2 of B-tile per chunk
    const int lm = threadIdx.x >> 3;   // 0..31
    const int lk = threadIdx.x & 7;    // 0..7

    // per-thread top-5 lists for its 4 rows
    float lv[4][KNN];
    int   li[4][KNN];
#pragma unroll
    for (int m = 0; m < 4; ++m)
#pragma unroll
        for (int s = 0; s < KNN; ++s) { lv[m][s] = 3.4e38f; li[m][s] = 0x7fffffff; }

    float sqr[4];
#pragma unroll
    for (int m = 0; m < 4; ++m) sqr[m] = g_sq[rowBase + ty * 4 + m];

    const float* Arow0 = X + (size_t)(rowBase + lm)      * DIMX + lk;
    const float* Arow1 = X + (size_t)(rowBase + lm + 32) * DIMX + lk;

    for (int ct = 0; ct < NPTS / TILE; ++ct) {
        const int colBase = ct * TILE;
        const float* Brow0 = X + (size_t)(colBase + lm)      * DIMX + lk;
        const float* Brow1 = X + (size_t)(colBase + lm + 32) * DIMX + lk;

        unsigned long long acc[4][2];
#pragma unroll
        for (int m = 0; m < 4; ++m) { acc[m][0] = 0ull; acc[m][1] = 0ull; }

        // preload chunk 0
        float a0 = Arow0[0], a1 = Arow1[0], b0 = Brow0[0], b1 = Brow1[0];

        for (int kc = 0; kc < DIMX / BK; ++kc) {
            __syncthreads();
            As[lk][lm] = a0; As[lk][lm + 32] = a1;
            Bs[lk][lm] = b0; Bs[lk][lm + 32] = b1;
            __syncthreads();
            if (kc + 1 < DIMX / BK) {
                int off = (kc + 1) * BK;
                a0 = Arow0[off]; a1 = Arow1[off];
                b0 = Brow0[off]; b1 = Brow1[off];
            }
#pragma unroll
            for (int kk = 0; kk < BK; ++kk) {
                float4 av = *(const float4*)&As[kk][ty * 4];
                float4 bv = *(const float4*)&Bs[kk][tx * 4];
                unsigned long long bp0 = pack2(bv.x, bv.y);
                unsigned long long bp1 = pack2(bv.z, bv.w);
                unsigned long long am;
                am = pack2(av.x, av.x); FMA2(acc[0][0], am, bp0); FMA2(acc[0][1], am, bp1);
                am = pack2(av.y, av.y); FMA2(acc[1][0], am, bp0); FMA2(acc[1][1], am, bp1);
                am = pack2(av.z, av.z); FMA2(acc[2][0], am, bp0); FMA2(acc[2][1], am, bp1);
                am = pack2(av.w, av.w); FMA2(acc[3][0], am, bp0); FMA2(acc[3][1], am, bp1);
            }
        }

        // epilogue: distances + top-5 update
        float sqc[4];
#pragma unroll
        for (int nn = 0; nn < 4; ++nn) sqc[nn] = __ldg(&g_sq[colBase + tx * 4 + nn]);
#pragma unroll
        for (int m = 0; m < 4; ++m) {
            const int r = rowBase + ty * 4 + m;
            float cv[4];
            unpack2(acc[m][0], cv[0], cv[1]);
            unpack2(acc[m][1], cv[2], cv[3]);
#pragma unroll
            for (int nn = 0; nn < 4; ++nn) {
                int cidx = colBase + tx * 4 + nn;
                float d2 = sqr[m] + sqc[nn] - 2.f * cv[nn];
                if (cidx != r) insert5(lv[m], li[m], d2, cidx);
            }
        }
    }

    // xor-hypercube merge across the 16 column-group threads (same ty share rows)
#pragma unroll
    for (int d = 1; d < 16; d <<= 1) {
#pragma unroll
        for (int m = 0; m < 4; ++m) {
            float sv[KNN]; int si[KNN];
#pragma unroll
            for (int s = 0; s < KNN; ++s) { sv[s] = lv[m][s]; si[s] = li[m][s]; }
#pragma unroll
            for (int s = 0; s < KNN; ++s) {
                float rv = __shfl_xor_sync(0xffffffffu, sv[s], d);
                int   ri = __shfl_xor_sync(0xffffffffu, si[s], d);
                insert5(lv[m], li[m], rv, ri);
            }
        }
    }

    if (tx == 0) {
#pragma unroll
        for (int m = 0; m < 4; ++m) {
            const int r = rowBase + ty * 4 + m;
            float vK = sqrtf(fmaxf(lv[m][KNN - 1], 0.f)) + EPSF;
            float lgK = log10f(vK);
            float lid = 0.f;
#pragma unroll
            for (int s = 0; s < KNN; ++s) {
                float v = sqrtf(fmaxf(lv[m][s], 0.f)) + EPSF;
                lid += lgK - log10f(v);
                g_nn[r * KNN + s] = li[m][s];
            }
            g_lidX[r] = lid;
        }
    }
}

// ---- kernel C: z-distances at NN indices, lid_Z, per-row squared diff ----
__global__ void zlid_kernel(const float* __restrict__ Z) {
    int warp = (blockIdx.x * blockDim.x + threadIdx.x) >> 5;
    int lane = threadIdx.x & 31;
    if (warp >= NPTS) return;
    const int r = warp;
    float z0 = Z[(size_t)r * DIMZ + lane];
    float z1 = Z[(size_t)r * DIMZ + 32 + lane];
    float e[KNN];
#pragma unroll
    for (int s = 0; s < KNN; ++s) {
        int m = g_nn[r * KNN + s];
        float d0 = z0 - Z[(size_t)m * DIMZ + lane];
        float d1 = z1 - Z[(size_t)m * DIMZ + 32 + lane];
        float ss = fmaf(d0, d0, d1 * d1);
#pragma unroll
        for (int o = 16; o > 0; o >>= 1) ss += __shfl_xor_sync(0xffffffffu, ss, o);
        e[s] = sqrtf(ss) + EPSF;
    }
    if (lane == 0) {
        float lgK = log10f(e[KNN - 1]);
        float lidZ = 0.f;
#pragma unroll
        for (int s = 0; s < KNN; ++s) lidZ += lgK - log10f(e[s]);
        float d = g_lidX[r] - lidZ;
        g_diff2[r] = d * d;
    }
}

// ---- kernel D: deterministic fixed-tree reduction + final scale ----
__global__ void reduce_kernel(float* __restrict__ out) {
    __shared__ float sh[1024];
    int t = threadIdx.x;
    float s = 0.f;
    for (int i = t; i < NPTS; i += 1024) s += g_diff2[i];
    sh[t] = s;
    __syncthreads();
    for (int o = 512; o > 0; o >>= 1) {
        if (t < o) sh[t] += sh[t + o];
        __syncthreads();
    }
    if (t == 0) out[0] = sh[0] * (1.f / ((float)NPTS * KNN * 10.f));
}

extern "C" void kernel_launch(void* const* d_in, const int* in_sizes, int n_in,
                              void* d_out, int out_size) {
    const float* X = (const float*)d_in[0];   // (8192, 256)
    const float* Z = (const float*)d_in[1];   // (8192, 64)
    float* out = (float*)d_out;

    sq_kernel<<<NPTS / 8, 256>>>(X);
    knn_kernel<<<NPTS / TILE, 256>>>(X);
    zlid_kernel<<<NPTS / 8, 256>>>(Z);
    reduce_kernel<<<1, 1024>>>(out);
}

// round 4
// speedup vs baseline: 2.8795x; 2.8795x over previous
#include <cuda_runtime.h>
#include <cuda_bf16.h>
#include <cstdint>

#define NPTS 8192
#define DIMX 256
#define DIMZ 64
#define KNN  5
#define TOPT 8
#define EPSF 1e-7f

#define MT 64
#define NT 64
#define NTILES 64            // 4096 cols per half / NT

// ---- scratch ----
__device__ float g_sq[NPTS];
__device__ float g_lidX[NPTS];
__device__ int   g_nn[NPTS * KNN];
__device__ float g_diff2[NPTS];
__device__ __nv_bfloat16 g_xbf[NPTS * DIMX];
__device__ int   g_cand[NPTS][2 * TOPT];

__device__ __forceinline__ uint32_t smem_u32(const void* p) {
    uint32_t a;
    asm("{ .reg .u64 t; cvta.to.shared.u64 t, %1; cvt.u32.u64 %0, t; }" : "=r"(a) : "l"(p));
    return a;
}

#define LDSM_X4(r0, r1, r2, r3, addr) \
    asm volatile("ldmatrix.sync.aligned.m8n8.x4.shared.b16 {%0,%1,%2,%3}, [%4];" \
                 : "=r"(r0), "=r"(r1), "=r"(r2), "=r"(r3) : "r"(addr))

#define MMA16816(c, a0, a1, a2, a3, b0, b1) \
    asm volatile("mma.sync.aligned.m16n8k16.row.col.f32.bf16.bf16.f32 " \
                 "{%0,%1,%2,%3}, {%4,%5,%6,%7}, {%8,%9}, {%0,%1,%2,%3};" \
                 : "+f"((c)[0]), "+f"((c)[1]), "+f"((c)[2]), "+f"((c)[3]) \
                 : "r"(a0), "r"(a1), "r"(a2), "r"(a3), "r"(b0), "r"(b1))

// ---- ordered inserts (lexicographic (value,index): matches jax top_k ties) ----
__device__ __forceinline__ bool lessp(float v, int i, float v2, int i2) {
    return (v < v2) || (v == v2 && i < i2);
}
__device__ __forceinline__ void insert8(float lv[TOPT], int li[TOPT], float v, int idx) {
    if (lessp(v, idx, lv[TOPT - 1], li[TOPT - 1])) {
        lv[TOPT - 1] = v; li[TOPT - 1] = idx;
#pragma unroll
        for (int s = TOPT - 1; s > 0; --s) {
            if (lessp(lv[s], li[s], lv[s - 1], li[s - 1])) {
                float tv = lv[s]; lv[s] = lv[s - 1]; lv[s - 1] = tv;
                int   ti = li[s]; li[s] = li[s - 1]; li[s - 1] = ti;
            }
        }
    }
}
__device__ __forceinline__ void insert5(float lv[KNN], int li[KNN], float v, int idx) {
    if (lessp(v, idx, lv[KNN - 1], li[KNN - 1])) {
        lv[KNN - 1] = v; li[KNN - 1] = idx;
#pragma unroll
        for (int s = KNN - 1; s > 0; --s) {
            if (lessp(lv[s], li[s], lv[s - 1], li[s - 1])) {
                float tv = lv[s]; lv[s] = lv[s - 1]; lv[s - 1] = tv;
                int   ti = li[s]; li[s] = li[s - 1]; li[s - 1] = ti;
            }
        }
    }
}

// ================= fp32 -> bf16 =================
__global__ void cvt_kernel(const float* __restrict__ X) {
    int i = blockIdx.x * blockDim.x + threadIdx.x;
    if (i >= NPTS * DIMX / 4) return;
    float4 v = ((const float4*)X)[i];
    ((__nv_bfloat162*)g_xbf)[2 * i]     = __floats2bfloat162_rn(v.x, v.y);
    ((__nv_bfloat162*)g_xbf)[2 * i + 1] = __floats2bfloat162_rn(v.z, v.w);
}

// ================= squared row norms =================
__global__ void sq_kernel(const float* __restrict__ X) {
    int warp = (blockIdx.x * blockDim.x + threadIdx.x) >> 5;
    int lane = threadIdx.x & 31;
    if (warp >= NPTS) return;
    const float* row = X + (size_t)warp * DIMX;
    float s = 0.f;
#pragma unroll
    for (int t = 0; t < DIMX / 32; ++t) { float v = row[lane + 32 * t]; s = fmaf(v, v, s); }
#pragma unroll
    for (int o = 16; o > 0; o >>= 1) s += __shfl_xor_sync(0xffffffffu, s, o);
    if (lane == 0) g_sq[warp] = s;
}

// ================= HMMA screening: 64x64 tile, 48KB static smem =================
__global__ __launch_bounds__(128) void screen_kernel() {
    __shared__ __align__(16) uint8_t smA[MT * 512];   // 64 rows x 256 bf16, XOR-swizzled
    __shared__ __align__(16) uint8_t smB[NT * 256];   // 64 rows x 128 bf16 (one k-chunk)

    const int tid = threadIdx.x;
    const int wid = tid >> 5;
    const int lane = tid & 31;
    const int mt = blockIdx.x >> 1;
    const int half = blockIdx.x & 1;
    const int rowBase = mt * MT;
    const int colHalf = half * (NPTS / 2);

    // ---- stage resident A tile: 64 rows x 32 chunks(16B), chunk' = chunk ^ (row&7) ----
#pragma unroll
    for (int it = 0; it < 16; ++it) {
        int linear = it * 128 + tid;
        int r = linear >> 5, cc = linear & 31;
        uint4 v = *(const uint4*)(g_xbf + (size_t)(rowBase + r) * DIMX + cc * 8);
        *(uint4*)(smA + r * 512 + (((uint32_t)cc ^ (r & 7)) << 4)) = v;
    }

    // ldmatrix address precompute
    const uint32_t aRowBase = smem_u32(smA) + (uint32_t)(wid * 16 + (lane & 15)) * 512;
    const uint32_t aSw = (uint32_t)((wid * 16 + (lane & 15)) & 7) << 4;
    const uint32_t aHi = (uint32_t)(lane >> 4) << 4;

    const int bn = (lane & 7) + ((lane >> 4) << 3);
    const uint32_t bBase = smem_u32(smB) + (uint32_t)bn * 256;
    const uint32_t bSw = (uint32_t)(bn & 7) << 4;
    const uint32_t bHi = (uint32_t)((lane >> 3) & 1) << 4;

    const int mrow0 = rowBase + wid * 16 + (lane >> 2);
    const int mrow1 = mrow0 + 8;

    float lv[2][TOPT]; int li[2][TOPT];
#pragma unroll
    for (int m = 0; m < 2; ++m)
#pragma unroll
        for (int s = 0; s < TOPT; ++s) { lv[m][s] = 3.4e38f; li[m][s] = 0x7fffffff; }

    for (int ct = 0; ct < NTILES; ++ct) {
        const int colBase = colHalf + ct * NT;

        float c[8][4];
#pragma unroll
        for (int j = 0; j < 8; ++j)
#pragma unroll
            for (int q = 0; q < 4; ++q) c[j][q] = 0.f;

#pragma unroll
        for (int kc = 0; kc < 2; ++kc) {
            __syncthreads();
            // stage B chunk: 64 rows x 16 chunks(16B)
#pragma unroll
            for (int it = 0; it < 8; ++it) {
                int linear = it * 128 + tid;
                int n = linear >> 4, cc = linear & 15;
                uint4 v = *(const uint4*)(g_xbf + (size_t)(colBase + n) * DIMX + kc * 128 + cc * 8);
                *(uint4*)(smB + n * 256 + (((uint32_t)cc ^ (n & 7)) << 4)) = v;
            }
            __syncthreads();

#pragma unroll
            for (int ksc = 0; ksc < 8; ++ksc) {
                uint32_t a0, a1, a2, a3;
                LDSM_X4(a0, a1, a2, a3, aRowBase + ((((uint32_t)(kc * 8 + ksc) * 32) + aHi) ^ aSw));
#pragma unroll
                for (int p = 0; p < 4; ++p) {
                    uint32_t b0, b1, b2, b3;
                    LDSM_X4(b0, b1, b2, b3, bBase + p * 4096 + ((((uint32_t)ksc * 32) + bHi) ^ bSw));
                    MMA16816(c[2 * p],     a0, a1, a2, a3, b0, b1);
                    MMA16816(c[2 * p + 1], a0, a1, a2, a3, b2, b3);
                }
            }
        }

        // epilogue: key = sq[c] - 2*dot (row term rank-invariant), top-8 update
#pragma unroll
        for (int j = 0; j < 8; ++j) {
            const int cb = colBase + j * 8 + 2 * (lane & 3);
            float2 s2 = __ldg((const float2*)&g_sq[j * 8 + 2 * (lane & 3) + colBase]);
            float k00 = fmaf(-2.f, c[j][0], s2.x);
            float k01 = fmaf(-2.f, c[j][1], s2.y);
            float k10 = fmaf(-2.f, c[j][2], s2.x);
            float k11 = fmaf(-2.f, c[j][3], s2.y);
            if (cb     != mrow0) insert8(lv[0], li[0], k00, cb);
            if (cb + 1 != mrow0) insert8(lv[0], li[0], k01, cb + 1);
            if (cb     != mrow1) insert8(lv[1], li[1], k10, cb);
            if (cb + 1 != mrow1) insert8(lv[1], li[1], k11, cb + 1);
        }
    }

    // merge across the 4 lane-quad threads sharing these rows
#pragma unroll
    for (int d = 1; d < 4; d <<= 1) {
#pragma unroll
        for (int m = 0; m < 2; ++m) {
            float sv[TOPT]; int si[TOPT];
#pragma unroll
            for (int s = 0; s < TOPT; ++s) { sv[s] = lv[m][s]; si[s] = li[m][s]; }
#pragma unroll
            for (int s = 0; s < TOPT; ++s) {
                float rv = __shfl_xor_sync(0xffffffffu, sv[s], d);
                int   ri = __shfl_xor_sync(0xffffffffu, si[s], d);
                insert8(lv[m], li[m], rv, ri);
            }
        }
    }

    if ((lane & 3) == 0) {
#pragma unroll
        for (int s = 0; s < TOPT; ++s) {
            g_cand[mrow0][half * TOPT + s] = li[0][s];
            g_cand[mrow1][half * TOPT + s] = li[1][s];
        }
    }
}

// ================= exact fp32 re-rank + lid_X =================
__global__ void rerank_kernel(const float* __restrict__ X) {
    int warp = (blockIdx.x * blockDim.x + threadIdx.x) >> 5;
    int lane = threadIdx.x & 31;
    if (warp >= NPTS) return;
    const int row = warp;
    float xi[8];
#pragma unroll
    for (int t = 0; t < 8; ++t) xi[t] = X[(size_t)row * DIMX + lane + 32 * t];
    const float sqr = g_sq[row];

    float lv[KNN]; int li[KNN];
#pragma unroll
    for (int s = 0; s < KNN; ++s) { lv[s] = 3.4e38f; li[s] = 0x7fffffff; }

#pragma unroll
    for (int s = 0; s < 2 * TOPT; ++s) {
        int j = g_cand[row][s];
        const float* xr = X + (size_t)j * DIMX;
        float d = 0.f;
#pragma unroll
        for (int t = 0; t < 8; ++t) d = fmaf(xi[t], xr[lane + 32 * t], d);
#pragma unroll
        for (int o = 16; o > 0; o >>= 1) d += __shfl_xor_sync(0xffffffffu, d, o);
        float d2 = sqr + g_sq[j] - 2.f * d;
        insert5(lv, li, d2, j);
    }

    if (lane == 0) {
        float vK = sqrtf(fmaxf(lv[KNN - 1], 0.f)) + EPSF;
        float lgK = log10f(vK);
        float lid = 0.f;
#pragma unroll
        for (int s = 0; s < KNN; ++s) {
            float v = sqrtf(fmaxf(lv[s], 0.f)) + EPSF;
            lid += lgK - log10f(v);
            g_nn[row * KNN + s] = li[s];
        }
        g_lidX[row] = lid;
    }
}

// ================= z-distances at NN, lid_Z, squared diff =================
__global__ void zlid_kernel(const float* __restrict__ Z) {
    int warp = (blockIdx.x * blockDim.x + threadIdx.x) >> 5;
    int lane = threadIdx.x & 31;
    if (warp >= NPTS) return;
    const int r = warp;
    float z0 = Z[(size_t)r * DIMZ + lane];
    float z1 = Z[(size_t)r * DIMZ + 32 + lane];
    float e[KNN];
#pragma unroll
    for (int s = 0; s < KNN; ++s) {
        int m = g_nn[r * KNN + s];
        float d0 = z0 - Z[(size_t)m * DIMZ + lane];
        float d1 = z1 - Z[(size_t)m * DIMZ + 32 + lane];
        float ss = fmaf(d0, d0, d1 * d1);
#pragma unroll
        for (int o = 16; o > 0; o >>= 1) ss += __shfl_xor_sync(0xffffffffu, ss, o);
        e[s] = sqrtf(ss) + EPSF;
    }
    if (lane == 0) {
        float lgK = log10f(e[KNN - 1]);
        float lidZ = 0.f;
#pragma unroll
        for (int s = 0; s < KNN; ++s) lidZ += lgK - log10f(e[s]);
        float d = g_lidX[r] - lidZ;
        g_diff2[r] = d * d;
    }
}

// ================= deterministic reduction =================
__global__ void reduce_kernel(float* __restrict__ out) {
    __shared__ float sh[1024];
    int t = threadIdx.x;
    float s = 0.f;
    for (int i = t; i < NPTS; i += 1024) s += g_diff2[i];
    sh[t] = s;
    __syncthreads();
    for (int o = 512; o > 0; o >>= 1) {
        if (t < o) sh[t] += sh[t + o];
        __syncthreads();
    }
    if (t == 0) out[0] = sh[0] * (1.f / ((float)NPTS * KNN * 10.f));
}

extern "C" void kernel_launch(void* const* d_in, const int* in_sizes, int n_in,
                              void* d_out, int out_size) {
    const float* X = (const float*)d_in[0];   // (8192, 256)
    const float* Z = (const float*)d_in[1];   // (8192, 64)
    float* out = (float*)d_out;

    cvt_kernel<<<(NPTS * DIMX / 4 + 255) / 256, 256>>>(X);
    sq_kernel<<<NPTS / 8, 256>>>(X);
    screen_kernel<<<(NPTS / MT) * 2, 128>>>();
    rerank_kernel<<<NPTS / 8, 256>>>(X);
    zlid_kernel<<<NPTS / 8, 256>>>(Z);
    reduce_kernel<<<1, 1024>>>(out);
}

// round 5
// speedup vs baseline: 3.4721x; 1.2058x over previous
#include <cuda_runtime.h>
#include <cuda_bf16.h>
#include <cstdint>

#define NPTS 8192
#define DIMX 256
#define DIMZ 64
#define KNN  5
#define EPSF 1e-7f

#define NTILE 128            // 8192 / 64 row-tiles
#define NPAIRS (NTILE * (NTILE + 1) / 2)   // 8256
#define PTOP 6               // per-tile partial top
#define GTOP 8               // merged global candidates

// ---- scratch ----
__device__ float g_sq[NPTS];
__device__ float g_lidX[NPTS];
__device__ int   g_nn[NPTS * KNN];
__device__ float g_diff2[NPTS];
__device__ __nv_bfloat16 g_xbf[NPTS * DIMX];
__device__ float          g_pv[(size_t)NPTS * NTILE * PTOP];   // 25.2 MB
__device__ unsigned short g_pi[(size_t)NPTS * NTILE * PTOP];   // 12.6 MB
__device__ int   g_cand[NPTS][GTOP];

__device__ __forceinline__ uint32_t smem_u32(const void* p) {
    uint32_t a;
    asm("{ .reg .u64 t; cvta.to.shared.u64 t, %1; cvt.u32.u64 %0, t; }" : "=r"(a) : "l"(p));
    return a;
}

#define LDSM_X4(r0, r1, r2, r3, addr) \
    asm volatile("ldmatrix.sync.aligned.m8n8.x4.shared.b16 {%0,%1,%2,%3}, [%4];" \
                 : "=r"(r0), "=r"(r1), "=r"(r2), "=r"(r3) : "r"(addr))

#define MMA16816(c, a0, a1, a2, a3, b0, b1) \
    asm volatile("mma.sync.aligned.m16n8k16.row.col.f32.bf16.bf16.f32 " \
                 "{%0,%1,%2,%3}, {%4,%5,%6,%7}, {%8,%9}, {%0,%1,%2,%3};" \
                 : "+f"((c)[0]), "+f"((c)[1]), "+f"((c)[2]), "+f"((c)[3]) \
                 : "r"(a0), "r"(a1), "r"(a2), "r"(a3), "r"(b0), "r"(b1))

// ---- ordered insert, lexicographic (value,index): matches jax top_k ties ----
__device__ __forceinline__ bool lessp(float v, int i, float v2, int i2) {
    return (v < v2) || (v == v2 && i < i2);
}
template<int NL>
__device__ __forceinline__ void insertN(float lv[NL], int li[NL], float v, int idx) {
    if (lessp(v, idx, lv[NL - 1], li[NL - 1])) {
        lv[NL - 1] = v; li[NL - 1] = idx;
#pragma unroll
        for (int s = NL - 1; s > 0; --s) {
            if (lessp(lv[s], li[s], lv[s - 1], li[s - 1])) {
                float tv = lv[s]; lv[s] = lv[s - 1]; lv[s - 1] = tv;
                int   ti2 = li[s]; li[s] = li[s - 1]; li[s - 1] = ti2;
            }
        }
    }
}

// ================= fp32 -> bf16 =================
__global__ void cvt_kernel(const float* __restrict__ X) {
    int i = blockIdx.x * blockDim.x + threadIdx.x;
    if (i >= NPTS * DIMX / 4) return;
    float4 v = ((const float4*)X)[i];
    ((__nv_bfloat162*)g_xbf)[2 * i]     = __floats2bfloat162_rn(v.x, v.y);
    ((__nv_bfloat162*)g_xbf)[2 * i + 1] = __floats2bfloat162_rn(v.z, v.w);
}

// ================= squared row norms =================
__global__ void sq_kernel(const float* __restrict__ X) {
    int warp = (blockIdx.x * blockDim.x + threadIdx.x) >> 5;
    int lane = threadIdx.x & 31;
    if (warp >= NPTS) return;
    const float* row = X + (size_t)warp * DIMX;
    float s = 0.f;
#pragma unroll
    for (int t = 0; t < DIMX / 32; ++t) { float v = row[lane + 32 * t]; s = fmaf(v, v, s); }
#pragma unroll
    for (int o = 16; o > 0; o >>= 1) s += __shfl_xor_sync(0xffffffffu, s, o);
    if (lane == 0) g_sq[warp] = s;
}

// ====== symmetric tile-pair screen: C = Xi * Xj^T (64x64), both-side top-6 ======
__global__ __launch_bounds__(128) void screen_pair_kernel() {
    __shared__ __align__(16) uint8_t smA[64 * 128];   // 64 rows x 64 bf16 k-chunk
    __shared__ __align__(16) uint8_t smB[64 * 128];
    __shared__ float smC[64 * 65];                    // stride 65: conflict-free col scans
    __shared__ float sqI[64], sqJ[64];

    const int tid = threadIdx.x;
    const int wid = tid >> 5;
    const int lane = tid & 31;

    // ---- linear pair index -> (ti, tj), ti <= tj ----
    const int k = blockIdx.x;
    int i = (int)(128.5f - sqrtf(128.5f * 128.5f - 2.0f * (float)k));
    if (i < 0) i = 0; if (i > NTILE - 1) i = NTILE - 1;
    while (i > 0 && (i * NTILE - i * (i - 1) / 2) > k) --i;
    while (((i + 1) * NTILE - (i + 1) * i / 2) <= k) ++i;
    const int ti = i;
    const int tj = i + (k - (i * NTILE - i * (i - 1) / 2));
    const int rbI = ti * 64, rbJ = tj * 64;

    if (tid < 64) { sqI[tid] = g_sq[rbI + tid]; sqJ[tid] = g_sq[rbJ + tid]; }

    // staging map: thread loads rows rr+{0,16,32,48}, 16B-chunk cc of each 128B k-chunk row
    const int rr = tid >> 3, cc = tid & 7;

    uint4 pa[4], pb[4];
#pragma unroll
    for (int it = 0; it < 4; ++it) {
        pa[it] = *(const uint4*)(g_xbf + (size_t)(rbI + rr + it * 16) * DIMX + cc * 8);
        pb[it] = *(const uint4*)(g_xbf + (size_t)(rbJ + rr + it * 16) * DIMX + cc * 8);
    }

    float c[8][4];
#pragma unroll
    for (int j = 0; j < 8; ++j)
#pragma unroll
        for (int q = 0; q < 4; ++q) c[j][q] = 0.f;

    // ldmatrix address precompute (fragment scheme identical to R4 pass)
    const int rA = wid * 16 + (lane & 15);
    const uint32_t aRowB = smem_u32(smA) + (uint32_t)rA * 128;
    const uint32_t aSw = (uint32_t)(rA & 7);
    const uint32_t aHi = (uint32_t)(lane >> 4);
    const int bLane = (lane & 7) + ((lane >> 4) << 3);
    const uint32_t bRowB = smem_u32(smB) + (uint32_t)bLane * 128;
    const uint32_t bSw = (uint32_t)(lane & 7);
    const uint32_t bHi = (uint32_t)((lane >> 3) & 1);

    for (int kc = 0; kc < 4; ++kc) {
        __syncthreads();
#pragma unroll
        for (int it = 0; it < 4; ++it) {
            int r = rr + it * 16;
            *(uint4*)(smA + r * 128 + (((uint32_t)cc ^ (r & 7)) << 4)) = pa[it];
            *(uint4*)(smB + r * 128 + (((uint32_t)cc ^ (r & 7)) << 4)) = pb[it];
        }
        __syncthreads();
        if (kc < 3) {
#pragma unroll
            for (int it = 0; it < 4; ++it) {
                pa[it] = *(const uint4*)(g_xbf + (size_t)(rbI + rr + it * 16) * DIMX + (kc + 1) * 64 + cc * 8);
                pb[it] = *(const uint4*)(g_xbf + (size_t)(rbJ + rr + it * 16) * DIMX + (kc + 1) * 64 + cc * 8);
            }
        }
#pragma unroll
        for (int ks = 0; ks < 4; ++ks) {
            uint32_t a0, a1, a2, a3;
            uint32_t ccA = (uint32_t)(ks * 2) + aHi;
            LDSM_X4(a0, a1, a2, a3, aRowB + ((ccA ^ aSw) << 4));
            uint32_t ccB = ((uint32_t)(ks * 2) + bHi) ^ bSw;
#pragma unroll
            for (int p = 0; p < 4; ++p) {
                uint32_t b0, b1, b2, b3;
                LDSM_X4(b0, b1, b2, b3, bRowB + (uint32_t)p * 2048 + (ccB << 4));
                MMA16816(c[2 * p],     a0, a1, a2, a3, b0, b1);
                MMA16816(c[2 * p + 1], a0, a1, a2, a3, b2, b3);
            }
        }
    }

    // ---- stage C to smem (stride 65) ----
    {
        const int g = lane >> 2, tq = lane & 3;
        const int r0 = wid * 16 + g, r1 = r0 + 8;
#pragma unroll
        for (int j = 0; j < 8; ++j) {
            int col = j * 8 + 2 * tq;
            smC[r0 * 65 + col]     = c[j][0];
            smC[r0 * 65 + col + 1] = c[j][1];
            smC[r1 * 65 + col]     = c[j][2];
            smC[r1 * 65 + col + 1] = c[j][3];
        }
    }
    __syncthreads();

    // ---- row side: rows of ti vs cols of tj ----
    {
        const int r = tid >> 1, h = tid & 1;
        const int grow = rbI + r;
        float lv[PTOP]; int li[PTOP];
#pragma unroll
        for (int s = 0; s < PTOP; ++s) { lv[s] = 3.4e38f; li[s] = 0x7fffffff; }
        for (int s = 0; s < 32; ++s) {
            int cl = h * 32 + s;
            int idx = rbJ + cl;
            float key = fmaf(-2.f, smC[r * 65 + cl], sqJ[cl]);
            if (idx != grow) insertN<PTOP>(lv, li, key, idx);
        }
        // merge the two half-scans (tid pairs), snapshot first
        {
            float sv[PTOP]; int si[PTOP];
#pragma unroll
            for (int s = 0; s < PTOP; ++s) { sv[s] = lv[s]; si[s] = li[s]; }
#pragma unroll
            for (int s = 0; s < PTOP; ++s) {
                float rv = __shfl_xor_sync(0xffffffffu, sv[s], 1);
                int   ri = __shfl_xor_sync(0xffffffffu, si[s], 1);
                insertN<PTOP>(lv, li, rv, ri);
            }
        }
        if (h == 0) {
            size_t off = ((size_t)grow * NTILE + tj) * PTOP;
#pragma unroll
            for (int s = 0; s < PTOP; ++s) { g_pv[off + s] = lv[s]; g_pi[off + s] = (unsigned short)li[s]; }
        }
    }

    // ---- col side: rows of tj vs rows of ti (skip diagonal: row side covers it) ----
    if (ti != tj) {
        const int cix = tid >> 1, h = tid & 1;
        const int grow = rbJ + cix;
        float lv[PTOP]; int li[PTOP];
#pragma unroll
        for (int s = 0; s < PTOP; ++s) { lv[s] = 3.4e38f; li[s] = 0x7fffffff; }
        for (int s = 0; s < 32; ++s) {
            int rl = h * 32 + s;
            int idx = rbI + rl;
            float key = fmaf(-2.f, smC[rl * 65 + cix], sqI[rl]);
            insertN<PTOP>(lv, li, key, idx);   // idx != grow always off-diagonal
        }
        {
            float sv[PTOP]; int si[PTOP];
#pragma unroll
            for (int s = 0; s < PTOP; ++s) { sv[s] = lv[s]; si[s] = li[s]; }
#pragma unroll
            for (int s = 0; s < PTOP; ++s) {
                float rv = __shfl_xor_sync(0xffffffffu, sv[s], 1);
                int   ri = __shfl_xor_sync(0xffffffffu, si[s], 1);
                insertN<PTOP>(lv, li, rv, ri);
            }
        }
        if (h == 0) {
            size_t off = ((size_t)grow * NTILE + ti) * PTOP;
#pragma unroll
            for (int s = 0; s < PTOP; ++s) { g_pv[off + s] = lv[s]; g_pi[off + s] = (unsigned short)li[s]; }
        }
    }
}

// ================= merge 128 partials per row -> global top-8 =================
__global__ void merge_kernel() {
    int warp = (blockIdx.x * blockDim.x + threadIdx.x) >> 5;
    int lane = threadIdx.x & 31;
    if (warp >= NPTS) return;
    float lv[GTOP]; int li[GTOP];
#pragma unroll
    for (int s = 0; s < GTOP; ++s) { lv[s] = 3.4e38f; li[s] = 0x7fffffff; }
#pragma unroll
    for (int q = 0; q < 4; ++q) {
        int tile = lane + q * 32;
        size_t off = ((size_t)warp * NTILE + tile) * PTOP;
#pragma unroll
        for (int s = 0; s < PTOP; ++s)
            insertN<GTOP>(lv, li, g_pv[off + s], (int)g_pi[off + s]);
    }
#pragma unroll
    for (int d = 1; d < 32; d <<= 1) {
        float sv[GTOP]; int si[GTOP];
#pragma unroll
        for (int s = 0; s < GTOP; ++s) { sv[s] = lv[s]; si[s] = li[s]; }
#pragma unroll
        for (int s = 0; s < GTOP; ++s) {
            float rv = __shfl_xor_sync(0xffffffffu, sv[s], d);
            int   ri = __shfl_xor_sync(0xffffffffu, si[s], d);
            insertN<GTOP>(lv, li, rv, ri);
        }
    }
    if (lane == 0) {
#pragma unroll
        for (int s = 0; s < GTOP; ++s) g_cand[warp][s] = li[s];
    }
}

// ================= exact fp32 re-rank + lid_X =================
__global__ void rerank_kernel(const float* __restrict__ X) {
    int warp = (blockIdx.x * blockDim.x + threadIdx.x) >> 5;
    int lane = threadIdx.x & 31;
    if (warp >= NPTS) return;
    const int row = warp;
    float xi[8];
#pragma unroll
    for (int t = 0; t < 8; ++t) xi[t] = X[(size_t)row * DIMX + lane + 32 * t];
    const float sqr = g_sq[row];

    float lv[KNN]; int li[KNN];
#pragma unroll
    for (int s = 0; s < KNN; ++s) { lv[s] = 3.4e38f; li[s] = 0x7fffffff; }

#pragma unroll
    for (int s = 0; s < GTOP; ++s) {
        int j = g_cand[row][s];
        const float* xr = X + (size_t)j * DIMX;
        float d = 0.f;
#pragma unroll
        for (int t = 0; t < 8; ++t) d = fmaf(xi[t], xr[lane + 32 * t], d);
#pragma unroll
        for (int o = 16; o > 0; o >>= 1) d += __shfl_xor_sync(0xffffffffu, d, o);
        float d2 = sqr + g_sq[j] - 2.f * d;
        insertN<KNN>(lv, li, d2, j);
    }

    if (lane == 0) {
        float vK = sqrtf(fmaxf(lv[KNN - 1], 0.f)) + EPSF;
        float lgK = log10f(vK);
        float lid = 0.f;
#pragma unroll
        for (int s = 0; s < KNN; ++s) {
            float v = sqrtf(fmaxf(lv[s], 0.f)) + EPSF;
            lid += lgK - log10f(v);
            g_nn[row * KNN + s] = li[s];
        }
        g_lidX[row] = lid;
    }
}

// ================= z-distances at NN, lid_Z, squared diff =================
__global__ void zlid_kernel(const float* __restrict__ Z) {
    int warp = (blockIdx.x * blockDim.x + threadIdx.x) >> 5;
    int lane = threadIdx.x & 31;
    if (warp >= NPTS) return;
    const int r = warp;
    float z0 = Z[(size_t)r * DIMZ + lane];
    float z1 = Z[(size_t)r * DIMZ + 32 + lane];
    float e[KNN];
#pragma unroll
    for (int s = 0; s < KNN; ++s) {
        int m = g_nn[r * KNN + s];
        float d0 = z0 - Z[(size_t)m * DIMZ + lane];
        float d1 = z1 - Z[(size_t)m * DIMZ + 32 + lane];
        float ss = fmaf(d0, d0, d1 * d1);
#pragma unroll
        for (int o = 16; o > 0; o >>= 1) ss += __shfl_xor_sync(0xffffffffu, ss, o);
        e[s] = sqrtf(ss) + EPSF;
    }
    if (lane == 0) {
        float lgK = log10f(e[KNN - 1]);
        float lidZ = 0.f;
#pragma unroll
        for (int s = 0; s < KNN; ++s) lidZ += lgK - log10f(e[s]);
        float d = g_lidX[r] - lidZ;
        g_diff2[r] = d * d;
    }
}

// ================= deterministic reduction =================
__global__ void reduce_kernel(float* __restrict__ out) {
    __shared__ float sh[1024];
    int t = threadIdx.x;
    float s = 0.f;
    for (int i = t; i < NPTS; i += 1024) s += g_diff2[i];
    sh[t] = s;
    __syncthreads();
    for (int o = 512; o > 0; o >>= 1) {
        if (t < o) sh[t] += sh[t + o];
        __syncthreads();
    }
    if (t == 0) out[0] = sh[0] * (1.f / ((float)NPTS * KNN * 10.f));
}

extern "C" void kernel_launch(void* const* d_in, const int* in_sizes, int n_in,
                              void* d_out, int out_size) {
    const float* X = (const float*)d_in[0];   // (8192, 256)
    const float* Z = (const float*)d_in[1];   // (8192, 64)
    float* out = (float*)d_out;

    cvt_kernel<<<(NPTS * DIMX / 4 + 255) / 256, 256>>>(X);
    sq_kernel<<<NPTS / 8, 256>>>(X);
    screen_pair_kernel<<<NPAIRS, 128>>>();
    merge_kernel<<<NPTS / 8, 256>>>();
    rerank_kernel<<<NPTS / 8, 256>>>(X);
    zlid_kernel<<<NPTS / 8, 256>>>(Z);
    reduce_kernel<<<1, 1024>>>(out);
}

// round 6
// speedup vs baseline: 6.2075x; 1.7878x over previous
#include <cuda_runtime.h>
#include <cuda_bf16.h>
#include <cstdint>

#define NPTS 8192
#define DIMX 256
#define DIMZ 64
#define KNN  5
#define EPSF 1e-7f

#define NTILE 128                          // 8192 / 64 row-tiles
#define NPAIRS (NTILE * (NTILE + 1) / 2)   // 8256
#define PTOP 4                             // per-tile partial top (packed u64)
#define GTOP 8                             // merged global candidates

// ---- scratch ----
__device__ float g_sq[NPTS];
__device__ float g_lidX[NPTS];
__device__ int   g_nn[NPTS * KNN];
__device__ float g_diff2[NPTS];
__device__ __nv_bfloat16 g_xbf[NPTS * DIMX];
__device__ unsigned long long g_p[(size_t)NPTS * NTILE * PTOP];   // 33.5 MB
__device__ int   g_cand[NPTS][GTOP];

__device__ __forceinline__ uint32_t smem_u32(const void* p) {
    uint32_t a;
    asm("{ .reg .u64 t; cvta.to.shared.u64 t, %1; cvt.u32.u64 %0, t; }" : "=r"(a) : "l"(p));
    return a;
}

#define LDSM_X4(r0, r1, r2, r3, addr) \
    asm volatile("ldmatrix.sync.aligned.m8n8.x4.shared.b16 {%0,%1,%2,%3}, [%4];" \
                 : "=r"(r0), "=r"(r1), "=r"(r2), "=r"(r3) : "r"(addr))

#define MMA16816(c, a0, a1, a2, a3, b0, b1) \
    asm volatile("mma.sync.aligned.m16n8k16.row.col.f32.bf16.bf16.f32 " \
                 "{%0,%1,%2,%3}, {%4,%5,%6,%7}, {%8,%9}, {%0,%1,%2,%3};" \
                 : "+f"((c)[0]), "+f"((c)[1]), "+f"((c)[2]), "+f"((c)[3]) \
                 : "r"(a0), "r"(a1), "r"(a2), "r"(a3), "r"(b0), "r"(b1))

// monotone float->u32 encoding; key = (enc<<32)|idx  (u64 '<' == lexicographic (val,idx))
__device__ __forceinline__ unsigned long long packkey(float v, int idx) {
    uint32_t u = __float_as_uint(v);
    u = (u >> 31) ? ~u : (u | 0x80000000u);
    return ((unsigned long long)u << 32) | (uint32_t)idx;
}
template<int NL>
__device__ __forceinline__ void insertU(unsigned long long l[NL], unsigned long long v) {
    if (v < l[NL - 1]) {
        l[NL - 1] = v;
#pragma unroll
        for (int s = NL - 1; s > 0; --s) {
            if (l[s] < l[s - 1]) { unsigned long long t = l[s]; l[s] = l[s - 1]; l[s - 1] = t; }
        }
    }
}
// exact-domain insert for rerank (float,int)
__device__ __forceinline__ bool lessp(float v, int i, float v2, int i2) {
    return (v < v2) || (v == v2 && i < i2);
}
__device__ __forceinline__ void insert5(float lv[KNN], int li[KNN], float v, int idx) {
    if (lessp(v, idx, lv[KNN - 1], li[KNN - 1])) {
        lv[KNN - 1] = v; li[KNN - 1] = idx;
#pragma unroll
        for (int s = KNN - 1; s > 0; --s) {
            if (lessp(lv[s], li[s], lv[s - 1], li[s - 1])) {
                float tv = lv[s]; lv[s] = lv[s - 1]; lv[s - 1] = tv;
                int   ti = li[s]; li[s] = li[s - 1]; li[s - 1] = ti;
            }
        }
    }
}

// ================= fp32 -> bf16 =================
__global__ void cvt_kernel(const float* __restrict__ X) {
    int i = blockIdx.x * blockDim.x + threadIdx.x;
    if (i >= NPTS * DIMX / 4) return;
    float4 v = ((const float4*)X)[i];
    ((__nv_bfloat162*)g_xbf)[2 * i]     = __floats2bfloat162_rn(v.x, v.y);
    ((__nv_bfloat162*)g_xbf)[2 * i + 1] = __floats2bfloat162_rn(v.z, v.w);
}

// ================= squared row norms =================
__global__ void sq_kernel(const float* __restrict__ X) {
    int warp = (blockIdx.x * blockDim.x + threadIdx.x) >> 5;
    int lane = threadIdx.x & 31;
    if (warp >= NPTS) return;
    const float* row = X + (size_t)warp * DIMX;
    float s = 0.f;
#pragma unroll
    for (int t = 0; t < DIMX / 32; ++t) { float v = row[lane + 32 * t]; s = fmaf(v, v, s); }
#pragma unroll
    for (int o = 16; o > 0; o >>= 1) s += __shfl_xor_sync(0xffffffffu, s, o);
    if (lane == 0) g_sq[warp] = s;
}

// ====== symmetric tile-pair screen: 256 thr, warp tile 16x32, packed partial top-4 ======
__global__ __launch_bounds__(256) void screen_pair_kernel() {
    __shared__ __align__(16) uint8_t smA[64 * 128];   // 64 rows x 64 bf16 k-chunk
    __shared__ __align__(16) uint8_t smB[64 * 128];
    __shared__ float smC[64 * 65];
    __shared__ float sqI[64], sqJ[64];

    const int tid = threadIdx.x;
    const int wid = tid >> 5;
    const int lane = tid & 31;

    // ---- linear pair index -> (ti, tj), ti <= tj ----
    const int k = blockIdx.x;
    int i = (int)(128.5f - sqrtf(128.5f * 128.5f - 2.0f * (float)k));
    if (i < 0) i = 0; if (i > NTILE - 1) i = NTILE - 1;
    while (i > 0 && (i * NTILE - i * (i - 1) / 2) > k) --i;
    while (((i + 1) * NTILE - (i + 1) * i / 2) <= k) ++i;
    const int ti = i;
    const int tj = i + (k - (i * NTILE - i * (i - 1) / 2));
    const int rbI = ti * 64, rbJ = tj * 64;

    if (tid < 64) { sqI[tid] = g_sq[rbI + tid]; sqJ[tid] = g_sq[rbJ + tid]; }

    // staging map: 512 16B-chunks per tile-chunk; thread handles chunk tid and tid+256
    const int rr = tid >> 3, cc = tid & 7;   // r in 0..31, +32 for second

    uint4 pa[2], pb[2];
#pragma unroll
    for (int it = 0; it < 2; ++it) {
        pa[it] = *(const uint4*)(g_xbf + (size_t)(rbI + rr + it * 32) * DIMX + cc * 8);
        pb[it] = *(const uint4*)(g_xbf + (size_t)(rbJ + rr + it * 32) * DIMX + cc * 8);
    }

    float c[4][4];
#pragma unroll
    for (int j = 0; j < 4; ++j)
#pragma unroll
        for (int q = 0; q < 4; ++q) c[j][q] = 0.f;

    // fragment addressing: warp (wid&3) -> row group, (wid>>2) -> col half
    const int rA = (wid & 3) * 16 + (lane & 15);
    const uint32_t aRowB = smem_u32(smA) + (uint32_t)rA * 128;
    const uint32_t aSw = (uint32_t)(rA & 7);
    const uint32_t aHi = (uint32_t)(lane >> 4);
    const int bLane = (lane & 7) + ((lane >> 4) << 3);
    const uint32_t bRowB = smem_u32(smB) + (uint32_t)bLane * 128;
    const uint32_t bSw = (uint32_t)(lane & 7);
    const uint32_t bHi = (uint32_t)((lane >> 3) & 1);
    const uint32_t bBlk = (uint32_t)(wid >> 2) * 2;   // 16-col block base

    for (int kc = 0; kc < 4; ++kc) {
        __syncthreads();
#pragma unroll
        for (int it = 0; it < 2; ++it) {
            int r = rr + it * 32;
            *(uint4*)(smA + r * 128 + (((uint32_t)cc ^ (r & 7)) << 4)) = pa[it];
            *(uint4*)(smB + r * 128 + (((uint32_t)cc ^ (r & 7)) << 4)) = pb[it];
        }
        __syncthreads();
        if (kc < 3) {
#pragma unroll
            for (int it = 0; it < 2; ++it) {
                pa[it] = *(const uint4*)(g_xbf + (size_t)(rbI + rr + it * 32) * DIMX + (kc + 1) * 64 + cc * 8);
                pb[it] = *(const uint4*)(g_xbf + (size_t)(rbJ + rr + it * 32) * DIMX + (kc + 1) * 64 + cc * 8);
            }
        }
#pragma unroll
        for (int ks = 0; ks < 4; ++ks) {
            uint32_t a0, a1, a2, a3;
            LDSM_X4(a0, a1, a2, a3, aRowB + ((((uint32_t)ks * 2 + aHi) ^ aSw) << 4));
            uint32_t ccB = (((uint32_t)ks * 2 + bHi) ^ bSw) << 4;
#pragma unroll
            for (int p = 0; p < 2; ++p) {
                uint32_t b0, b1, b2, b3;
                LDSM_X4(b0, b1, b2, b3, bRowB + (bBlk + p) * 2048 + ccB);
                MMA16816(c[2 * p],     a0, a1, a2, a3, b0, b1);
                MMA16816(c[2 * p + 1], a0, a1, a2, a3, b2, b3);
            }
        }
    }

    // ---- stage C to smem (stride 65) ----
    {
        const int r0 = (wid & 3) * 16 + (lane >> 2), r1 = r0 + 8;
        const int cq = (wid >> 2) * 32 + 2 * (lane & 3);
#pragma unroll
        for (int j = 0; j < 4; ++j) {
            int col = cq + j * 8;
            smC[r0 * 65 + col]     = c[j][0];
            smC[r0 * 65 + col + 1] = c[j][1];
            smC[r1 * 65 + col]     = c[j][2];
            smC[r1 * 65 + col + 1] = c[j][3];
        }
    }
    __syncthreads();

    // ---- row side: 4 scanners per row, 16 cols each ----
    {
        const int r = tid >> 2, h = tid & 3;
        const int grow = rbI + r;
        unsigned long long l[PTOP];
#pragma unroll
        for (int s = 0; s < PTOP; ++s) l[s] = 0xFFFFFFFFFFFFFFFFull;
#pragma unroll
        for (int s = 0; s < 16; ++s) {
            int cl = h * 16 + s;
            int idx = rbJ + cl;
            if (idx != grow)
                insertU<PTOP>(l, packkey(fmaf(-2.f, smC[r * 65 + cl], sqJ[cl]), idx));
        }
#pragma unroll
        for (int d = 1; d < 4; d <<= 1) {
            unsigned long long sv[PTOP];
#pragma unroll
            for (int s = 0; s < PTOP; ++s) sv[s] = l[s];
#pragma unroll
            for (int s = 0; s < PTOP; ++s)
                insertU<PTOP>(l, __shfl_xor_sync(0xffffffffu, sv[s], d));
        }
        if (h == 0) {
            unsigned long long* dst = &g_p[((size_t)grow * NTILE + tj) * PTOP];
            ((ulonglong2*)dst)[0] = make_ulonglong2(l[0], l[1]);
            ((ulonglong2*)dst)[1] = make_ulonglong2(l[2], l[3]);
        }
    }

    // ---- col side (skip diagonal pair) ----
    if (ti != tj) {
        const int c2 = tid >> 2, h = tid & 3;
        const int grow = rbJ + c2;
        unsigned long long l[PTOP];
#pragma unroll
        for (int s = 0; s < PTOP; ++s) l[s] = 0xFFFFFFFFFFFFFFFFull;
#pragma unroll
        for (int s = 0; s < 16; ++s) {
            int rl = h * 16 + s;
            insertU<PTOP>(l, packkey(fmaf(-2.f, smC[rl * 65 + c2], sqI[rl]), rbI + rl));
        }
#pragma unroll
        for (int d = 1; d < 4; d <<= 1) {
            unsigned long long sv[PTOP];
#pragma unroll
            for (int s = 0; s < PTOP; ++s) sv[s] = l[s];
#pragma unroll
            for (int s = 0; s < PTOP; ++s)
                insertU<PTOP>(l, __shfl_xor_sync(0xffffffffu, sv[s], d));
        }
        if (h == 0) {
            unsigned long long* dst = &g_p[((size_t)grow * NTILE + ti) * PTOP];
            ((ulonglong2*)dst)[0] = make_ulonglong2(l[0], l[1]);
            ((ulonglong2*)dst)[1] = make_ulonglong2(l[2], l[3]);
        }
    }
}

// ================= merge 128x4 packed partials per row -> global top-8 =================
__global__ void merge_kernel() {
    int warp = (blockIdx.x * blockDim.x + threadIdx.x) >> 5;
    int lane = threadIdx.x & 31;
    if (warp >= NPTS) return;
    unsigned long long l[GTOP];
#pragma unroll
    for (int s = 0; s < GTOP; ++s) l[s] = 0xFFFFFFFFFFFFFFFFull;
#pragma unroll
    for (int q = 0; q < 4; ++q) {
        const unsigned long long* src = &g_p[((size_t)warp * NTILE + lane + q * 32) * PTOP];
        ulonglong2 v0 = ((const ulonglong2*)src)[0];
        ulonglong2 v1 = ((const ulonglong2*)src)[1];
        insertU<GTOP>(l, v0.x); insertU<GTOP>(l, v0.y);
        insertU<GTOP>(l, v1.x); insertU<GTOP>(l, v1.y);
    }
#pragma unroll
    for (int d = 1; d < 32; d <<= 1) {
        unsigned long long sv[GTOP];
#pragma unroll
        for (int s = 0; s < GTOP; ++s) sv[s] = l[s];
#pragma unroll
        for (int s = 0; s < GTOP; ++s)
            insertU<GTOP>(l, __shfl_xor_sync(0xffffffffu, sv[s], d));
    }
    if (lane == 0) {
#pragma unroll
        for (int s = 0; s < GTOP; ++s) g_cand[warp][s] = (int)(uint32_t)(l[s] & 0xffffffffu);
    }
}

// ================= exact fp32 re-rank + lid_X =================
__global__ void rerank_kernel(const float* __restrict__ X) {
    int warp = (blockIdx.x * blockDim.x + threadIdx.x) >> 5;
    int lane = threadIdx.x & 31;
    if (warp >= NPTS) return;
    const int row = warp;
    float xi[8];
#pragma unroll
    for (int t = 0; t < 8; ++t) xi[t] = X[(size_t)row * DIMX + lane + 32 * t];
    const float sqr = g_sq[row];

    float lv[KNN]; int li[KNN];
#pragma unroll
    for (int s = 0; s < KNN; ++s) { lv[s] = 3.4e38f; li[s] = 0x7fffffff; }

#pragma unroll
    for (int s = 0; s < GTOP; ++s) {
        int j = g_cand[row][s];
        const float* xr = X + (size_t)j * DIMX;
        float d = 0.f;
#pragma unroll
        for (int t = 0; t < 8; ++t) d = fmaf(xi[t], xr[lane + 32 * t], d);
#pragma unroll
        for (int o = 16; o > 0; o >>= 1) d += __shfl_xor_sync(0xffffffffu, d, o);
        float d2 = sqr + g_sq[j] - 2.f * d;
        insert5(lv, li, d2, j);
    }

    if (lane == 0) {
        float vK = sqrtf(fmaxf(lv[KNN - 1], 0.f)) + EPSF;
        float lgK = log10f(vK);
        float lid = 0.f;
#pragma unroll
        for (int s = 0; s < KNN; ++s) {
            float v = sqrtf(fmaxf(lv[s], 0.f)) + EPSF;
            lid += lgK - log10f(v);
            g_nn[row * KNN + s] = li[s];
        }
        g_lidX[row] = lid;
    }
}

// ================= z-distances at NN, lid_Z, squared diff =================
__global__ void zlid_kernel(const float* __restrict__ Z) {
    int warp = (blockIdx.x * blockDim.x + threadIdx.x) >> 5;
    int lane = threadIdx.x & 31;
    if (warp >= NPTS) return;
    const int r = warp;
    float z0 = Z[(size_t)r * DIMZ + lane];
    float z1 = Z[(size_t)r * DIMZ + 32 + lane];
    float e[KNN];
#pragma unroll
    for (int s = 0; s < KNN; ++s) {
        int m = g_nn[r * KNN + s];
        float d0 = z0 - Z[(size_t)m * DIMZ + lane];
        float d1 = z1 - Z[(size_t)m * DIMZ + 32 + lane];
        float ss = fmaf(d0, d0, d1 * d1);
#pragma unroll
        for (int o = 16; o > 0; o >>= 1) ss += __shfl_xor_sync(0xffffffffu, ss, o);
        e[s] = sqrtf(ss) + EPSF;
    }
    if (lane == 0) {
        float lgK = log10f(e[KNN - 1]);
        float lidZ = 0.f;
#pragma unroll
        for (int s = 0; s < KNN; ++s) lidZ += lgK - log10f(e[s]);
        float d = g_lidX[r] - lidZ;
        g_diff2[r] = d * d;
    }
}

// ================= deterministic reduction =================
__global__ void reduce_kernel(float* __restrict__ out) {
    __shared__ float sh[1024];
    int t = threadIdx.x;
    float s = 0.f;
    for (int i = t; i < NPTS; i += 1024) s += g_diff2[i];
    sh[t] = s;
    __syncthreads();
    for (int o = 512; o > 0; o >>= 1) {
        if (t < o) sh[t] += sh[t + o];
        __syncthreads();
    }
    if (t == 0) out[0] = sh[0] * (1.f / ((float)NPTS * KNN * 10.f));
}

extern "C" void kernel_launch(void* const* d_in, const int* in_sizes, int n_in,
                              void* d_out, int out_size) {
    const float* X = (const float*)d_in[0];   // (8192, 256)
    const float* Z = (const float*)d_in[1];   // (8192, 64)
    float* out = (float*)d_out;

    cvt_kernel<<<(NPTS * DIMX / 4 + 255) / 256, 256>>>(X);
    sq_kernel<<<NPTS / 8, 256>>>(X);
    screen_pair_kernel<<<NPAIRS, 256>>>();
    merge_kernel<<<NPTS / 8, 256>>>();
    rerank_kernel<<<NPTS / 8, 256>>>(X);
    zlid_kernel<<<NPTS / 8, 256>>>(Z);
    reduce_kernel<<<1, 1024>>>(out);
}